// round 4
// baseline (speedup 1.0000x reference)
#include <cuda_runtime.h>
#include <cuda_bf16.h>
#include <cstdint>

// ---------------------------------------------------------------------------
// Problem constants
// ---------------------------------------------------------------------------
#define BATCH 8
#define CH    512
#define LEN   8192
#define PADL  8
#define LPAD  (LEN + 2*PADL)          // 8208
#define KTOT  3072                    // 3 taps * 512 ch * 2 halves
#define WELEM (512*512*3)             // 786432 elems per weight tensor

// ---------------------------------------------------------------------------
// Scratch (device globals — no allocation allowed)
// ---------------------------------------------------------------------------
__device__ uint32_t       g_X2[(size_t)BATCH*CH*LPAD];   // split input  {hi,lo} u32
__device__ uint32_t       g_H2[(size_t)BATCH*CH*LPAD];   // split hidden {hi,lo} u32
__device__ __nv_bfloat16  g_Wq[(size_t)6*512*KTOT];      // ternary weights, k=(tap,c,half)
__device__ float          g_scales[6];
__device__ float          g_partial[6*64];

// ---------------------------------------------------------------------------
// Helpers
// ---------------------------------------------------------------------------
__device__ __forceinline__ uint32_t smem_u32(const void* p) {
    return (uint32_t)__cvta_generic_to_shared(p);
}
__device__ __forceinline__ uint32_t packsplit(float v) {
    __nv_bfloat16 h = __float2bfloat16(v);
    float r = v - __bfloat162float(h);
    __nv_bfloat16 lo = __float2bfloat16(r);
    return (uint32_t)__bfloat16_as_ushort(h) | ((uint32_t)__bfloat16_as_ushort(lo) << 16);
}
__device__ __forceinline__ void cp16(uint32_t dst, const void* src) {
    asm volatile("cp.async.cg.shared.global [%0], [%1], 16;\n" :: "r"(dst), "l"(src));
}
__device__ __forceinline__ void cp4(uint32_t dst, const void* src) {
    asm volatile("cp.async.ca.shared.global [%0], [%1], 4;\n" :: "r"(dst), "l"(src));
}
__device__ __forceinline__ void ldmA(uint32_t a[4], uint32_t addr) {
    asm volatile("ldmatrix.sync.aligned.m8n8.x4.shared.b16 {%0,%1,%2,%3}, [%4];\n"
                 : "=r"(a[0]), "=r"(a[1]), "=r"(a[2]), "=r"(a[3]) : "r"(addr));
}
__device__ __forceinline__ void mma16816(float c[4], const uint32_t a[4], const uint32_t b[2]) {
    asm volatile(
        "mma.sync.aligned.m16n8k16.row.col.f32.bf16.bf16.f32 "
        "{%0,%1,%2,%3}, {%4,%5,%6,%7}, {%8,%9}, {%0,%1,%2,%3};\n"
        : "+f"(c[0]), "+f"(c[1]), "+f"(c[2]), "+f"(c[3])
        : "r"(a[0]), "r"(a[1]), "r"(a[2]), "r"(a[3]), "r"(b[0]), "r"(b[1]));
}

// ---------------------------------------------------------------------------
// Weight prep: absmean scale (two-phase, deterministic), then ternarize
// ---------------------------------------------------------------------------
__global__ void scales_part_kernel(const float* w0, const float* w1, const float* w2,
                                   const float* w3, const float* w4, const float* w5) {
    const float* ws[6] = {w0, w1, w2, w3, w4, w5};
    const float* w = ws[blockIdx.y];
    __shared__ float red[256];
    const int chunk = WELEM / 64;                 // 12288
    int base = blockIdx.x * chunk;
    float s = 0.f;
    for (int i = threadIdx.x; i < chunk; i += 256) s += fabsf(w[base + i]);
    red[threadIdx.x] = s;
    __syncthreads();
    for (int o = 128; o; o >>= 1) {
        if (threadIdx.x < o) red[threadIdx.x] += red[threadIdx.x + o];
        __syncthreads();
    }
    if (threadIdx.x == 0) g_partial[blockIdx.y * 64 + blockIdx.x] = red[0];
}

__global__ void scales_fin_kernel() {
    __shared__ float red[64];
    red[threadIdx.x] = g_partial[blockIdx.x * 64 + threadIdx.x];
    __syncthreads();
    for (int o = 32; o; o >>= 1) {
        if (threadIdx.x < o) red[threadIdx.x] += red[threadIdx.x + o];
        __syncthreads();
    }
    if (threadIdx.x == 0) g_scales[blockIdx.x] = red[0] / (float)WELEM + 1e-5f;
}

__global__ void quant_kernel(const float* w0, const float* w1, const float* w2,
                             const float* w3, const float* w4, const float* w5) {
    const float* ws[6] = {w0, w1, w2, w3, w4, w5};
    size_t idx = (size_t)blockIdx.x * 256 + threadIdx.x;
    if (idx >= (size_t)6 * WELEM) return;
    int widx = (int)(idx / WELEM);
    int rem  = (int)(idx % WELEM);
    int o    = rem / 1536;
    int r2   = rem % 1536;
    int tap  = r2 / 512;
    int cc   = r2 % 512;
    float scale = g_scales[widx];
    float v = ws[widx][((size_t)o * 512 + cc) * 3 + tap];
    float q = rintf(v / scale);                   // round-half-even, matches jnp.round
    q = fminf(1.f, fmaxf(-1.f, q));
    __nv_bfloat16 qb = __float2bfloat16(q);       // exact for {-1,0,1}
    size_t dst = (size_t)widx * 512 * KTOT + (size_t)o * KTOT + (size_t)tap * 1024 + cc * 2;
    g_Wq[dst]     = qb;                           // half 0 (hi)
    g_Wq[dst + 1] = qb;                           // half 1 (lo)
}

// ---------------------------------------------------------------------------
// Split fp32 -> {hi,lo} bf16 pair, into padded halo layout (+ optional copy to out)
// grid: (ceil(LPAD/256), BATCH*CH)
// ---------------------------------------------------------------------------
__global__ void split_kernel(const float* __restrict__ src, float* __restrict__ cpy) {
    int p = blockIdx.x * 256 + threadIdx.x;
    if (p >= LPAD) return;
    size_t bc = blockIdx.y;
    int l = p - PADL;
    float v = 0.f;
    bool in = (l >= 0) && (l < LEN);
    if (in) v = src[bc * LEN + l];
    g_X2[bc * LPAD + p] = packsplit(v);
    if (cpy != nullptr && in) cpy[bc * LEN + l] = v;
}

// zero the halo of g_H2 (written only in-range by convA epilogue)
__global__ void zeropad_kernel() {
    size_t bc = blockIdx.x;
    int j = threadIdx.x;                          // 0..15
    int p = (j < 8) ? j : (LEN + j);              // 0..7 and 8200..8207
    g_H2[bc * LPAD + p] = 0u;
}

// ---------------------------------------------------------------------------
// GEMM conv kernel.  SRCSEL: 0 reads g_X2, 1 reads g_H2.
// RESID=false: epilogue = scale+bias+LeakyReLU -> split-store into g_H2
// RESID=true : epilogue = scale+bias+residual  -> fp32 store into outF
// grid: (LEN/128, 512/128, BATCH), block 256
// ---------------------------------------------------------------------------
template <bool RESID, int SRCSEL>
__global__ __launch_bounds__(256, 2)
void conv_kernel(const float* __restrict__ bias, int widx, int dil,
                 float* __restrict__ outF) {
    __shared__ __align__(16) __nv_bfloat16 As[2][128 * 40];   // 40 = 32 + 8 pad
    __shared__ __align__(16) uint32_t      Bs[2][16 * 132];   // 132 = 128 + 4 pad

    const int lBase = blockIdx.x * 128;
    const int oBase = blockIdx.y * 128;
    const int bIdx  = blockIdx.z;
    const int tid   = threadIdx.x;
    const int lane  = tid & 31;
    const int wid   = tid >> 5;
    const int wm    = wid >> 2;      // 0..1  (64 m-rows each)
    const int wn    = wid & 3;       // 0..3  (32 n-cols each)
    const int g     = lane >> 2;     // 0..7
    const int tq    = lane & 3;      // 0..3

    const __nv_bfloat16* Aw = g_Wq + (size_t)widx * 512 * KTOT;
    const uint32_t* __restrict__ Bin = (SRCSEL == 0) ? g_X2 : g_H2;

    uint32_t asB[2] = {smem_u32(&As[0][0]), smem_u32(&As[1][0])};
    uint32_t bsB[2] = {smem_u32(&Bs[0][0]), smem_u32(&Bs[1][0])};

    float c[4][4][4];
#pragma unroll
    for (int mi = 0; mi < 4; ++mi)
#pragma unroll
        for (int ni = 0; ni < 4; ++ni)
#pragma unroll
            for (int r = 0; r < 4; ++r) c[mi][ni][r] = 0.f;

    auto loadStage = [&](int st, int kc) {
        // ---- A tile: 128 rows x 32 bf16 (64B) -> 2 x cp.async.16 per thread
        {
            int q = tid * 2;
#pragma unroll
            for (int u = 0; u < 2; ++u, ++q) {
                int m   = q >> 2;
                int kch = q & 3;
                cp16(asB[st] + (uint32_t)(m * 40 + kch * 8) * 2,
                     Aw + (size_t)(oBase + m) * KTOT + kc * 32 + kch * 8);
            }
        }
        // ---- B tile: 16 pair-rows x 128 u32 -> 8 x cp.async.4 per thread
        {
            int tap   = kc >> 5;                  // 32 chunks per tap
            int cB    = (kc & 31) << 4;           // 16 channels per chunk
            int shift = (tap - 1) * dil;
            const uint32_t* srcBase =
                Bin + ((size_t)(bIdx * CH + cB)) * LPAD + (PADL + lBase + shift);
#pragma unroll
            for (int j = 0; j < 8; ++j) {
                int r = tid + 256 * j;
                int p = r >> 7;                   // pair-row 0..15
                int n = r & 127;
                cp4(bsB[st] + (uint32_t)(p * 132 + n) * 4,
                    srcBase + (size_t)p * LPAD + n);
            }
        }
        asm volatile("cp.async.commit_group;\n" ::: "memory");
    };

    auto mmaStage = [&](int st) {
#pragma unroll
        for (int s = 0; s < 2; ++s) {
            uint32_t afr[4][4];
#pragma unroll
            for (int mi = 0; mi < 4; ++mi) {
                uint32_t addr = asB[st] +
                    (uint32_t)(((wm * 64 + mi * 16 + (lane & 15)) * 40) +
                               s * 16 + ((lane >> 4) << 3)) * 2;
                ldmA(afr[mi], addr);
            }
            uint32_t bfr[4][2];
#pragma unroll
            for (int ni = 0; ni < 4; ++ni) {
                int col = wn * 32 + ni * 8 + g;
                bfr[ni][0] = Bs[st][(s * 8 + tq) * 132 + col];
                bfr[ni][1] = Bs[st][(s * 8 + 4 + tq) * 132 + col];
            }
#pragma unroll
            for (int mi = 0; mi < 4; ++mi)
#pragma unroll
                for (int ni = 0; ni < 4; ++ni)
                    mma16816(c[mi][ni], afr[mi], bfr[ni]);
        }
    };

    // ---- pipeline: 2 stages, 96 k-chunks
    loadStage(0, 0);
    for (int kc = 0; kc < 96; ++kc) {
        if (kc + 1 < 96) {
            loadStage((kc + 1) & 1, kc + 1);
            asm volatile("cp.async.wait_group 1;\n" ::: "memory");
        } else {
            asm volatile("cp.async.wait_group 0;\n" ::: "memory");
        }
        __syncthreads();
        mmaStage(kc & 1);
        __syncthreads();
    }

    // ---- epilogue
    const float scale = g_scales[widx];
#pragma unroll
    for (int mi = 0; mi < 4; ++mi) {
        int o0 = oBase + wm * 64 + mi * 16 + g;
        float bv0 = bias[o0];
        float bv1 = bias[o0 + 8];
#pragma unroll
        for (int ni = 0; ni < 4; ++ni) {
            int l = lBase + wn * 32 + ni * 8 + tq * 2;
            float v0 = c[mi][ni][0] * scale + bv0;
            float v1 = c[mi][ni][1] * scale + bv0;
            float v2 = c[mi][ni][2] * scale + bv1;
            float v3 = c[mi][ni][3] * scale + bv1;
            if (RESID) {
                size_t i0 = ((size_t)(bIdx * CH + o0)) * LEN + l;
                size_t i1 = ((size_t)(bIdx * CH + o0 + 8)) * LEN + l;
                float2 r0 = *(const float2*)(outF + i0);
                float2 r1 = *(const float2*)(outF + i1);
                *(float2*)(outF + i0) = make_float2(v0 + r0.x, v1 + r0.y);
                *(float2*)(outF + i1) = make_float2(v2 + r1.x, v3 + r1.y);
            } else {
                v0 = (v0 >= 0.f) ? v0 : 0.1f * v0;
                v1 = (v1 >= 0.f) ? v1 : 0.1f * v1;
                v2 = (v2 >= 0.f) ? v2 : 0.1f * v2;
                v3 = (v3 >= 0.f) ? v3 : 0.1f * v3;
                size_t i0 = ((size_t)(bIdx * CH + o0)) * LPAD + PADL + l;
                size_t i1 = ((size_t)(bIdx * CH + o0 + 8)) * LPAD + PADL + l;
                *(uint2*)(&g_H2[i0]) = make_uint2(packsplit(v0), packsplit(v1));
                *(uint2*)(&g_H2[i1]) = make_uint2(packsplit(v2), packsplit(v3));
            }
        }
    }
}

// ---------------------------------------------------------------------------
// Launch
// ---------------------------------------------------------------------------
extern "C" void kernel_launch(void* const* d_in, const int* in_sizes, int n_in,
                              void* d_out, int out_size) {
    const float* x = (const float*)d_in[0];
    const float* W[6];
    const float* Bv[6];
    for (int i = 0; i < 6; ++i) {
        W[i]  = (const float*)d_in[1 + 2 * i];
        Bv[i] = (const float*)d_in[2 + 2 * i];
    }
    float* out = (float*)d_out;

    // weight prep
    scales_part_kernel<<<dim3(64, 6), 256>>>(W[0], W[1], W[2], W[3], W[4], W[5]);
    scales_fin_kernel<<<6, 64>>>();
    {
        size_t total = (size_t)6 * WELEM;
        int blocks = (int)((total + 255) / 256);
        quant_kernel<<<blocks, 256>>>(W[0], W[1], W[2], W[3], W[4], W[5]);
    }
    zeropad_kernel<<<BATCH * CH, 16>>>();

    const dim3 cgrid(LEN / 128, CH / 128, BATCH);
    const dim3 sgrid((LPAD + 255) / 256, BATCH * CH);
    const int dils[3] = {1, 3, 5};

    for (int br = 0; br < 3; ++br) {
        // split current x (fp32) into hi/lo pairs; first branch also copies x -> out
        split_kernel<<<sgrid, 256>>>(br == 0 ? x : out, br == 0 ? out : nullptr);
        // conv A (dilated) + leaky + split-store -> g_H2
        conv_kernel<false, 0><<<cgrid, 256>>>(Bv[2 * br], 2 * br, dils[br], nullptr);
        // conv B (dense) + bias + residual -> out
        conv_kernel<true, 1><<<cgrid, 256>>>(Bv[2 * br + 1], 2 * br + 1, 1, out);
    }
}

// round 5
// speedup vs baseline: 1.0437x; 1.0437x over previous
#include <cuda_runtime.h>
#include <cuda_bf16.h>
#include <cstdint>

// ---------------------------------------------------------------------------
// Problem constants
// ---------------------------------------------------------------------------
#define BATCH 8
#define CH    512
#define LEN   8192
#define PADL  8
#define LPAD  (LEN + 2*PADL)          // 8208
#define KTOT  3072                    // 3 taps * 512 ch * 2 halves
#define WELEM (512*512*3)             // 786432 elems per weight tensor

// conv tiling
#define BM 128
#define BN 256
#define BK 64                         // k per chunk (32 u32 pair-rows)
#define NCHUNK (KTOT / BK)            // 48
#define STAGES 3
#define ASTR 72                       // A smem row stride (bf16): 64 + 8 pad
#define BSTR 264                      // B smem row stride (u32): 256 + 8 pad (==8 mod 32)
#define A_BYTES (BM * ASTR * 2)       // 18432
#define B_BYTES (32 * BSTR * 4)       // 33792
#define STAGE_BYTES (A_BYTES + B_BYTES)          // 52224
#define SMEM_TOTAL (STAGES * STAGE_BYTES)        // 156672

// ---------------------------------------------------------------------------
// Scratch (device globals — no allocation allowed)
// ---------------------------------------------------------------------------
__device__ uint32_t       g_X2[(size_t)BATCH*CH*LPAD];   // split input  {hi,lo} u32
__device__ uint32_t       g_H2[(size_t)BATCH*CH*LPAD];   // split hidden {hi,lo} u32
__device__ __nv_bfloat16  g_Wq[(size_t)6*512*KTOT];      // ternary weights, k=(tap,c,half)
__device__ float          g_scales[6];
__device__ float          g_partial[6*64];

// ---------------------------------------------------------------------------
// Helpers
// ---------------------------------------------------------------------------
__device__ __forceinline__ uint32_t smem_u32(const void* p) {
    return (uint32_t)__cvta_generic_to_shared(p);
}
__device__ __forceinline__ uint32_t packsplit(float v) {
    __nv_bfloat16 h = __float2bfloat16(v);
    float r = v - __bfloat162float(h);
    __nv_bfloat16 lo = __float2bfloat16(r);
    return (uint32_t)__bfloat16_as_ushort(h) | ((uint32_t)__bfloat16_as_ushort(lo) << 16);
}
__device__ __forceinline__ void cp16(uint32_t dst, const void* src) {
    asm volatile("cp.async.cg.shared.global [%0], [%1], 16;\n" :: "r"(dst), "l"(src));
}
__device__ __forceinline__ void cp4(uint32_t dst, const void* src) {
    asm volatile("cp.async.ca.shared.global [%0], [%1], 4;\n" :: "r"(dst), "l"(src));
}
__device__ __forceinline__ void ldmA(uint32_t a[4], uint32_t addr) {
    asm volatile("ldmatrix.sync.aligned.m8n8.x4.shared.b16 {%0,%1,%2,%3}, [%4];\n"
                 : "=r"(a[0]), "=r"(a[1]), "=r"(a[2]), "=r"(a[3]) : "r"(addr));
}
__device__ __forceinline__ void mma16816(float c[4], const uint32_t a[4], const uint32_t b[2]) {
    asm volatile(
        "mma.sync.aligned.m16n8k16.row.col.f32.bf16.bf16.f32 "
        "{%0,%1,%2,%3}, {%4,%5,%6,%7}, {%8,%9}, {%0,%1,%2,%3};\n"
        : "+f"(c[0]), "+f"(c[1]), "+f"(c[2]), "+f"(c[3])
        : "r"(a[0]), "r"(a[1]), "r"(a[2]), "r"(a[3]), "r"(b[0]), "r"(b[1]));
}

// ---------------------------------------------------------------------------
// Weight prep: absmean scale (two-phase, deterministic), then ternarize
// ---------------------------------------------------------------------------
__global__ void scales_part_kernel(const float* w0, const float* w1, const float* w2,
                                   const float* w3, const float* w4, const float* w5) {
    const float* ws[6] = {w0, w1, w2, w3, w4, w5};
    const float* w = ws[blockIdx.y];
    __shared__ float red[256];
    const int chunk = WELEM / 64;                 // 12288
    int base = blockIdx.x * chunk;
    float s = 0.f;
    for (int i = threadIdx.x; i < chunk; i += 256) s += fabsf(w[base + i]);
    red[threadIdx.x] = s;
    __syncthreads();
    for (int o = 128; o; o >>= 1) {
        if (threadIdx.x < o) red[threadIdx.x] += red[threadIdx.x + o];
        __syncthreads();
    }
    if (threadIdx.x == 0) g_partial[blockIdx.y * 64 + blockIdx.x] = red[0];
}

__global__ void scales_fin_kernel() {
    __shared__ float red[64];
    red[threadIdx.x] = g_partial[blockIdx.x * 64 + threadIdx.x];
    __syncthreads();
    for (int o = 32; o; o >>= 1) {
        if (threadIdx.x < o) red[threadIdx.x] += red[threadIdx.x + o];
        __syncthreads();
    }
    if (threadIdx.x == 0) g_scales[blockIdx.x] = red[0] / (float)WELEM + 1e-5f;
}

__global__ void quant_kernel(const float* w0, const float* w1, const float* w2,
                             const float* w3, const float* w4, const float* w5) {
    const float* ws[6] = {w0, w1, w2, w3, w4, w5};
    size_t idx = (size_t)blockIdx.x * 256 + threadIdx.x;
    if (idx >= (size_t)6 * WELEM) return;
    int widx = (int)(idx / WELEM);
    int rem  = (int)(idx % WELEM);
    int o    = rem / 1536;
    int r2   = rem % 1536;
    int tap  = r2 / 512;
    int cc   = r2 % 512;
    float scale = g_scales[widx];
    float v = ws[widx][((size_t)o * 512 + cc) * 3 + tap];
    float q = rintf(v / scale);                   // round-half-even, matches jnp.round
    q = fminf(1.f, fmaxf(-1.f, q));
    __nv_bfloat16 qb = __float2bfloat16(q);       // exact for {-1,0,1}
    size_t dst = (size_t)widx * 512 * KTOT + (size_t)o * KTOT + (size_t)tap * 1024 + cc * 2;
    g_Wq[dst]     = qb;                           // half 0 (hi)
    g_Wq[dst + 1] = qb;                           // half 1 (lo)
}

// ---------------------------------------------------------------------------
// Split fp32 -> {hi,lo} bf16 pair, into padded halo layout (+ optional copy to out)
// grid: (ceil(LPAD/256), BATCH*CH)
// ---------------------------------------------------------------------------
__global__ void split_kernel(const float* __restrict__ src, float* __restrict__ cpy) {
    int p = blockIdx.x * 256 + threadIdx.x;
    if (p >= LPAD) return;
    size_t bc = blockIdx.y;
    int l = p - PADL;
    float v = 0.f;
    bool in = (l >= 0) && (l < LEN);
    if (in) v = src[bc * LEN + l];
    g_X2[bc * LPAD + p] = packsplit(v);
    if (cpy != nullptr && in) cpy[bc * LEN + l] = v;
}

// zero the halo of g_H2 (written only in-range by convA epilogue)
__global__ void zeropad_kernel() {
    size_t bc = blockIdx.x;
    int j = threadIdx.x;                          // 0..15
    int p = (j < 8) ? j : (LEN + j);              // 0..7 and 8200..8207
    g_H2[bc * LPAD + p] = 0u;
}

// ---------------------------------------------------------------------------
// GEMM conv kernel.  SRCSEL: 0 reads g_X2, 1 reads g_H2.
// RESID=false: epilogue = scale+bias+LeakyReLU -> split-store into g_H2
// RESID=true : epilogue = scale+bias+residual  -> fp32 store into outF
// grid: (LEN/BN, CH/BM, BATCH), block 512, dynamic smem SMEM_TOTAL
// ---------------------------------------------------------------------------
template <bool RESID, int SRCSEL>
__global__ __launch_bounds__(512, 1)
void conv_kernel(const float* __restrict__ bias, int widx, int dil,
                 float* __restrict__ outF) {
    extern __shared__ char smem[];

    const int lBase = blockIdx.x * BN;
    const int oBase = blockIdx.y * BM;
    const int bIdx  = blockIdx.z;
    const int tid   = threadIdx.x;
    const int lane  = tid & 31;
    const int wid   = tid >> 5;      // 0..15
    const int wm    = wid >> 3;      // 0..1  (64 m-rows each)
    const int wn    = wid & 7;       // 0..7  (32 n-cols each)
    const int g     = lane >> 2;     // 0..7
    const int tq    = lane & 3;      // 0..3

    const __nv_bfloat16* Aw = g_Wq + (size_t)widx * 512 * KTOT;
    const uint32_t* __restrict__ Bin = (SRCSEL == 0) ? g_X2 : g_H2;

    uint32_t  aB[STAGES];
    uint32_t  bB[STAGES];
    uint32_t* bP[STAGES];
#pragma unroll
    for (int s = 0; s < STAGES; ++s) {
        char* stg = smem + s * STAGE_BYTES;
        aB[s] = smem_u32(stg);
        bB[s] = smem_u32(stg + A_BYTES);
        bP[s] = (uint32_t*)(stg + A_BYTES);
    }

    float c[4][4][4];
#pragma unroll
    for (int mi = 0; mi < 4; ++mi)
#pragma unroll
        for (int ni = 0; ni < 4; ++ni)
#pragma unroll
            for (int r = 0; r < 4; ++r) c[mi][ni][r] = 0.f;

    auto loadStage = [&](int st, int kc) {
        // ---- A tile: 128 rows x 64 bf16 -> 2 x cp.async.16 per thread (1024 total)
        {
            int q = tid * 2;
#pragma unroll
            for (int u = 0; u < 2; ++u, ++q) {
                int m   = q >> 3;                 // 0..127
                int kch = q & 7;                  // 0..7 (8 bf16 each)
                cp16(aB[st] + (uint32_t)(m * ASTR + kch * 8) * 2,
                     Aw + (size_t)(oBase + m) * KTOT + kc * BK + kch * 8);
            }
        }
        // ---- B tile: 32 pair-rows x 256 u32 -> 16 x cp.async.4 per thread
        {
            int tap   = kc >> 4;                  // 16 chunks per tap
            int cB    = (kc & 15) << 5;           // 32 channels per chunk
            int shift = (tap - 1) * dil;
            const uint32_t* srcBase =
                Bin + ((size_t)(bIdx * CH + cB)) * LPAD + (PADL + lBase + shift);
#pragma unroll
            for (int j = 0; j < 16; ++j) {
                int r = tid + 512 * j;
                int p = r >> 8;                   // pair-row 0..31
                int n = r & 255;
                cp4(bB[st] + (uint32_t)(p * BSTR + n) * 4,
                    srcBase + (size_t)p * LPAD + n);
            }
        }
    };

    auto mmaStage = [&](int st) {
        const uint32_t* Bsl = bP[st];
#pragma unroll
        for (int s = 0; s < 4; ++s) {             // 4 x k16 per BK=64 chunk
            uint32_t afr[4][4];
#pragma unroll
            for (int mi = 0; mi < 4; ++mi) {
                uint32_t addr = aB[st] +
                    (uint32_t)(((wm * 64 + mi * 16 + (lane & 15)) * ASTR) +
                               s * 16 + ((lane >> 4) << 3)) * 2;
                ldmA(afr[mi], addr);
            }
            uint32_t bfr[4][2];
#pragma unroll
            for (int ni = 0; ni < 4; ++ni) {
                int col = wn * 32 + ni * 8 + g;
                bfr[ni][0] = Bsl[(s * 8 + tq) * BSTR + col];
                bfr[ni][1] = Bsl[(s * 8 + 4 + tq) * BSTR + col];
            }
#pragma unroll
            for (int mi = 0; mi < 4; ++mi)
#pragma unroll
                for (int ni = 0; ni < 4; ++ni)
                    mma16816(c[mi][ni], afr[mi], bfr[ni]);
        }
    };

    // ---- pipeline: 3 stages, 48 k-chunks, one barrier per chunk
    loadStage(0, 0);
    asm volatile("cp.async.commit_group;\n" ::: "memory");
    loadStage(1, 1);
    asm volatile("cp.async.commit_group;\n" ::: "memory");

    for (int kc = 0; kc < NCHUNK; ++kc) {
        asm volatile("cp.async.wait_group 1;\n" ::: "memory");  // stage kc ready
        __syncthreads();                                        // all warps done with stage (kc-1)%3
        if (kc + 2 < NCHUNK) loadStage((kc + 2) % STAGES, kc + 2);
        asm volatile("cp.async.commit_group;\n" ::: "memory");  // (possibly empty) keeps count uniform
        mmaStage(kc % STAGES);
    }

    // ---- epilogue
    const float scale = g_scales[widx];
#pragma unroll
    for (int mi = 0; mi < 4; ++mi) {
        int o0 = oBase + wm * 64 + mi * 16 + g;
        float bv0 = bias[o0];
        float bv1 = bias[o0 + 8];
#pragma unroll
        for (int ni = 0; ni < 4; ++ni) {
            int l = lBase + wn * 32 + ni * 8 + tq * 2;
            float v0 = c[mi][ni][0] * scale + bv0;
            float v1 = c[mi][ni][1] * scale + bv0;
            float v2 = c[mi][ni][2] * scale + bv1;
            float v3 = c[mi][ni][3] * scale + bv1;
            if (RESID) {
                size_t i0 = ((size_t)(bIdx * CH + o0)) * LEN + l;
                size_t i1 = ((size_t)(bIdx * CH + o0 + 8)) * LEN + l;
                float2 r0 = *(const float2*)(outF + i0);
                float2 r1 = *(const float2*)(outF + i1);
                *(float2*)(outF + i0) = make_float2(v0 + r0.x, v1 + r0.y);
                *(float2*)(outF + i1) = make_float2(v2 + r1.x, v3 + r1.y);
            } else {
                v0 = (v0 >= 0.f) ? v0 : 0.1f * v0;
                v1 = (v1 >= 0.f) ? v1 : 0.1f * v1;
                v2 = (v2 >= 0.f) ? v2 : 0.1f * v2;
                v3 = (v3 >= 0.f) ? v3 : 0.1f * v3;
                size_t i0 = ((size_t)(bIdx * CH + o0)) * LPAD + PADL + l;
                size_t i1 = ((size_t)(bIdx * CH + o0 + 8)) * LPAD + PADL + l;
                *(uint2*)(&g_H2[i0]) = make_uint2(packsplit(v0), packsplit(v1));
                *(uint2*)(&g_H2[i1]) = make_uint2(packsplit(v2), packsplit(v3));
            }
        }
    }
}

// ---------------------------------------------------------------------------
// Launch
// ---------------------------------------------------------------------------
extern "C" void kernel_launch(void* const* d_in, const int* in_sizes, int n_in,
                              void* d_out, int out_size) {
    const float* x = (const float*)d_in[0];
    const float* W[6];
    const float* Bv[6];
    for (int i = 0; i < 6; ++i) {
        W[i]  = (const float*)d_in[1 + 2 * i];
        Bv[i] = (const float*)d_in[2 + 2 * i];
    }
    float* out = (float*)d_out;

    // opt-in to >48KB dynamic smem (eager host-side call; idempotent, not captured)
    cudaFuncSetAttribute(conv_kernel<false, 0>,
                         cudaFuncAttributeMaxDynamicSharedMemorySize, SMEM_TOTAL);
    cudaFuncSetAttribute(conv_kernel<true, 1>,
                         cudaFuncAttributeMaxDynamicSharedMemorySize, SMEM_TOTAL);

    // weight prep
    scales_part_kernel<<<dim3(64, 6), 256>>>(W[0], W[1], W[2], W[3], W[4], W[5]);
    scales_fin_kernel<<<6, 64>>>();
    {
        size_t total = (size_t)6 * WELEM;
        int blocks = (int)((total + 255) / 256);
        quant_kernel<<<blocks, 256>>>(W[0], W[1], W[2], W[3], W[4], W[5]);
    }
    zeropad_kernel<<<BATCH * CH, 16>>>();

    const dim3 cgrid(LEN / BN, CH / BM, BATCH);
    const dim3 sgrid((LPAD + 255) / 256, BATCH * CH);
    const int dils[3] = {1, 3, 5};

    for (int br = 0; br < 3; ++br) {
        // split current x (fp32) into hi/lo pairs; first branch also copies x -> out
        split_kernel<<<sgrid, 256>>>(br == 0 ? x : out, br == 0 ? out : nullptr);
        // conv A (dilated) + leaky + split-store -> g_H2
        conv_kernel<false, 0><<<cgrid, 512, SMEM_TOTAL>>>(Bv[2 * br], 2 * br, dils[br], nullptr);
        // conv B (dense) + bias + residual -> out
        conv_kernel<true, 1><<<cgrid, 512, SMEM_TOTAL>>>(Bv[2 * br + 1], 2 * br + 1, 1, out);
    }
}